// round 8
// baseline (speedup 1.0000x reference)
#include <cuda_runtime.h>
#include <cuda_fp16.h>
#include <cstdint>
#include <math.h>

// ---------------- problem constants ----------------
#define LTOT 2304      // IMG + TXT
#define IMGN 2048
#define TXTN 256
#define HIDN 3072
#define NH   24
#define DH   128
#define MLPN 12288
#define REFN 512
#define CATN (HIDN + MLPN)        // 15360
#define L1N  (3*HIDN + MLPN)      // 21504
#define HD   (NH*DH)              // 3072

// ---------------- helpers ----------------
__device__ __forceinline__ uint32_t smem_u32(const void* p) {
    uint32_t a;
    asm("{ .reg .u64 t; cvta.to.shared.u64 t, %1; cvt.u32.u64 %0, t; }" : "=r"(a) : "l"(p));
    return a;
}
#define SMEM_SWIZZLE_128B(byte_offset) ((byte_offset) ^ (((byte_offset) >> 3) & 0x70))

__device__ __forceinline__ void cp16(uint32_t saddr, const void* g) {
    asm volatile("cp.async.cg.shared.global [%0], [%1], 16;" :: "r"(saddr), "l"(g));
}
#define CP_COMMIT() asm volatile("cp.async.commit_group;" ::: "memory")
#define CP_WAIT1()  asm volatile("cp.async.wait_group 1;" ::: "memory")
#define CP_WAIT0()  asm volatile("cp.async.wait_group 0;" ::: "memory")

__device__ __forceinline__ void ldsm4(uint32_t r[4], uint32_t addr) {
    asm volatile("ldmatrix.sync.aligned.m8n8.x4.shared.b16 {%0,%1,%2,%3}, [%4];"
        : "=r"(r[0]), "=r"(r[1]), "=r"(r[2]), "=r"(r[3]) : "r"(addr));
}
__device__ __forceinline__ void ldsm4t(uint32_t r[4], uint32_t addr) {
    asm volatile("ldmatrix.sync.aligned.m8n8.x4.trans.shared.b16 {%0,%1,%2,%3}, [%4];"
        : "=r"(r[0]), "=r"(r[1]), "=r"(r[2]), "=r"(r[3]) : "r"(addr));
}
__device__ __forceinline__ void mma16816(float c[4], const uint32_t a[4], const uint32_t b[2]) {
    asm volatile("mma.sync.aligned.m16n8k16.row.col.f32.f16.f16.f32 "
        "{%0,%1,%2,%3}, {%4,%5,%6,%7}, {%8,%9}, {%0,%1,%2,%3};"
        : "+f"(c[0]), "+f"(c[1]), "+f"(c[2]), "+f"(c[3])
        : "r"(a[0]), "r"(a[1]), "r"(a[2]), "r"(a[3]), "r"(b[0]), "r"(b[1]));
}
__device__ __forceinline__ uint32_t packh2(float a, float b) {
    __half2 t = __floats2half2_rn(a, b);
    return *(uint32_t*)&t;
}
__device__ __forceinline__ float gelu_f(float x) {
    return 0.5f*x*(1.f + tanhf(0.7978845608028654f*(x + 0.044715f*x*x*x)));
}

// ---------------- device scratch ----------------
__device__ float g_sv[HIDN];
__device__ float g_mod[3*HIDN];
__device__ __half g_xb[(size_t)LTOT*HIDN];
__device__ __half g_lin1h[(size_t)LTOT*(3*HIDN)];    // qkv part, fp16
__device__ __half g_qb[(size_t)LTOT*HIDN];
__device__ __half g_kb[(size_t)LTOT*HIDN];
__device__ __half g_vb[(size_t)LTOT*HIDN];
__device__ __half g_cat[(size_t)LTOT*CATN];
__device__ float g_refk[(size_t)REFN*HIDN];
__device__ float g_refv[(size_t)REFN*HIDN];
__device__ __half g_refkb[(size_t)REFN*HIDN];
__device__ __half g_refvb[(size_t)REFN*HIDN];
__device__ __half g_rlb[(size_t)REFN*HIDN];
__device__ __half g_w1b[(size_t)L1N*HIDN];
__device__ __half g_w2b[(size_t)HIDN*CATN];
__device__ __half g_wkb[(size_t)HIDN*HIDN];
__device__ __half g_wvb[(size_t)HIDN*HIDN];

// ---------------- small kernels ----------------
__global__ void silu_kernel(const float* __restrict__ v, float* __restrict__ sv) {
    int i = blockIdx.x*blockDim.x + threadIdx.x;
    if (i < HIDN) { float x = v[i]; sv[i] = x / (1.f + __expf(-x)); }
}

__global__ void modproj_kernel(const float* __restrict__ sv, const float* __restrict__ w,
                               const float* __restrict__ b, float* __restrict__ mod) {
    __shared__ float red[8][32];
    int nx = threadIdx.x & 31, ky = threadIdx.x >> 5;
    int n = blockIdx.x*32 + nx;
    float acc = 0.f;
    for (int k = ky; k < HIDN; k += 8)
        acc = fmaf(sv[k], w[(size_t)k*(3*HIDN) + n], acc);
    red[ky][nx] = acc;
    __syncthreads();
    if (ky == 0) {
        float s = acc;
#pragma unroll
        for (int i = 1; i < 8; i++) s += red[i][nx];
        mod[n] = s + b[n];
    }
}

__global__ void ln_mod_kernel(const float* __restrict__ x, const float* __restrict__ mod,
                              __half* __restrict__ xb) {
    int row = blockIdx.x;
    int tid = threadIdx.x;
    const float* xr = x + (size_t)row*HIDN;
    float s = 0.f, s2 = 0.f;
    for (int i = tid; i < HIDN; i += 256) { float v = xr[i]; s += v; s2 += v*v; }
    __shared__ float rs[256], rs2[256];
    rs[tid] = s; rs2[tid] = s2; __syncthreads();
    for (int o = 128; o > 0; o >>= 1) {
        if (tid < o) { rs[tid] += rs[tid+o]; rs2[tid] += rs2[tid+o]; }
        __syncthreads();
    }
    float mean = rs[0] * (1.f/HIDN);
    float var  = rs2[0] * (1.f/HIDN) - mean*mean;
    float inv  = rsqrtf(var + 1e-6f);
    for (int i = tid; i < HIDN; i += 256) {
        float v = (xr[i] - mean) * inv;
        v = v * (1.f + mod[HIDN + i]) + mod[i];
        xb[(size_t)row*HIDN + i] = __float2half_rn(v);
    }
}

// transpose + convert: w[K,N] fp32 -> [N,K] fp16
__global__ void wcvtT_kernel(const float* __restrict__ w, __half* __restrict__ o,
                             int K, int N) {
    __shared__ __half t[32][66];
    int n0 = blockIdx.x*32, k0 = blockIdx.y*64;
    int tx = threadIdx.x, ty = threadIdx.y;  // 32 x 8
#pragma unroll
    for (int i = 0; i < 8; i++) {
        int k = ty + i*8;
        t[tx][k] = __float2half_rn(w[(size_t)(k0+k)*N + n0 + tx]);
    }
    __syncthreads();
#pragma unroll
    for (int i = 0; i < 4; i++) {
        int n = i*8 + ty;
        __half2 v = *(__half2*)&t[n][2*tx];
        *(__half2*)&o[(size_t)(n0+n)*K + k0 + 2*tx] = v;
    }
}

__global__ void cvt_h_kernel(const float* __restrict__ src, __half* __restrict__ dst,
                             size_t n) {
    size_t i = (size_t)blockIdx.x*blockDim.x + threadIdx.x;
    if (i < n) dst[i] = __float2half_rn(src[i]);
}

// ---------------- HMMA fp16 GEMM, 128x256 CTA tile, 64x64 warp tiles ----------------
// C[M,N] = A[M,K] @ B[N,K]^T + bias
// mode 0 (PLAIN): C fp32 stride N
// mode 1 (LIN1):  cols < 3*HIDN -> lin1h fp16 (stride 3*HIDN); cols >= -> gelu fp16 into cat
// mode 2 (OUT):   C = xres + gate[n]*(acc+bias), fp32, stride N
#define GA_SZ    16384
#define GS_STAGE 49152           // A 16KB + B 32KB
#define GK_SMEM_TOTAL (2*GS_STAGE)   // 96KB

__global__ void __launch_bounds__(256, 1) tc_gemm_kernel(
    const __half* __restrict__ A, const __half* __restrict__ B,
    const float* __restrict__ bias, float* __restrict__ C,
    __half* __restrict__ lin1h, __half* __restrict__ cat,
    const float* __restrict__ xres, const float* __restrict__ gate,
    int M, int N, int K, int m_tiles, int mode)
{
    extern __shared__ char smem[];
    uint32_t sb = smem_u32(smem);
    int tid = threadIdx.x;
    int lane = tid & 31, wid = tid >> 5;
    int wm = wid >> 2, wn = wid & 3;   // warp tile: rows wm*64, cols wn*64

    int mi = blockIdx.x % m_tiles;
    int ni = blockIdx.x / m_tiles;
    int bm = mi * 128, bn = ni * 256;

    float acc[4][8][4];
#pragma unroll
    for (int i = 0; i < 4; i++)
#pragma unroll
        for (int j = 0; j < 8; j++)
#pragma unroll
            for (int r = 0; r < 4; r++) acc[i][j][r] = 0.f;

    int NC = K >> 6;

    auto load_stage = [&](int st, int k0) {
        uint32_t base = sb + st*GS_STAGE;
#pragma unroll
        for (int q = 0; q < 4; q++) {
            int idx = q*256 + tid;
            int r = idx >> 3;
            int ch = (idx & 7) << 4;
            uint32_t sw = SMEM_SWIZZLE_128B((uint32_t)(r*128 + ch));
            cp16(base + sw, (const char*)(A + (size_t)(bm + r)*K + k0) + ch);
        }
#pragma unroll
        for (int q = 0; q < 8; q++) {
            int idx = q*256 + tid;
            int r = idx >> 3;
            int ch = (idx & 7) << 4;
            uint32_t sw = SMEM_SWIZZLE_128B((uint32_t)(r*128 + ch));
            cp16(base + GA_SZ + sw, (const char*)(B + (size_t)(bn + r)*K + k0) + ch);
        }
    };

    load_stage(0, 0);
    CP_COMMIT();

    for (int c = 0; c < NC; c++) {
        if (c + 1 < NC) { load_stage((c+1) & 1, (c+1) << 6); CP_COMMIT(); CP_WAIT1(); }
        else            { CP_WAIT0(); }
        __syncthreads();

        uint32_t base = sb + (c & 1)*GS_STAGE;
        int arow = wm*64 + (lane & 15);
        int apl  = ((lane >> 4) & 1) << 4;
        int brow = wn*64 + ((lane >> 4) & 1)*8 + (lane & 7);
        int bpl  = ((lane >> 3) & 1) << 4;
#pragma unroll
        for (int kk = 0; kk < 4; kk++) {
            uint32_t a[4][4], b[4][4];
#pragma unroll
            for (int i = 0; i < 4; i++) {
                uint32_t sw = SMEM_SWIZZLE_128B((uint32_t)((arow + i*16)*128 + kk*32 + apl));
                ldsm4(a[i], base + sw);
            }
#pragma unroll
            for (int j = 0; j < 4; j++) {
                uint32_t sw = SMEM_SWIZZLE_128B((uint32_t)((brow + j*16)*128 + kk*32 + bpl));
                ldsm4(b[j], base + GA_SZ + sw);
            }
#pragma unroll
            for (int i = 0; i < 4; i++)
#pragma unroll
                for (int j = 0; j < 4; j++) {
                    mma16816(acc[i][2*j],   a[i], b[j]);
                    mma16816(acc[i][2*j+1], a[i], b[j] + 2);
                }
        }
        __syncthreads();
    }

#pragma unroll
    for (int i = 0; i < 4; i++) {
        int m0 = bm + wm*64 + i*16 + (lane >> 2);
#pragma unroll
        for (int j = 0; j < 8; j++) {
            int n = bn + wn*64 + j*8 + (lane & 3)*2;
            float b0 = bias[n], b1 = bias[n+1];
            float v00 = acc[i][j][0] + b0, v01 = acc[i][j][1] + b1;
            float v10 = acc[i][j][2] + b0, v11 = acc[i][j][3] + b1;
            if (mode == 0) {
                float* c0 = C + (size_t)m0*N + n;
                float* c1 = C + (size_t)(m0+8)*N + n;
                c0[0] = v00; c0[1] = v01; c1[0] = v10; c1[1] = v11;
            } else if (mode == 1) {
                if (bn < 3*HIDN) {
                    *(__half2*)(lin1h + (size_t)m0*(3*HIDN) + n)     = *(__half2*)&(uint32_t&)*(uint32_t[]){packh2(v00, v01)};
                    *(__half2*)(lin1h + (size_t)(m0+8)*(3*HIDN) + n) = *(__half2*)&(uint32_t&)*(uint32_t[]){packh2(v10, v11)};
                } else {
                    int nc = HIDN + (n - 3*HIDN);
                    uint32_t g0 = packh2(gelu_f(v00), gelu_f(v01));
                    uint32_t g1 = packh2(gelu_f(v10), gelu_f(v11));
                    *(uint32_t*)(cat + (size_t)m0*CATN + nc)     = g0;
                    *(uint32_t*)(cat + (size_t)(m0+8)*CATN + nc) = g1;
                }
            } else {
                float g0 = gate[n], g1 = gate[n+1];
                const float* x0 = xres + (size_t)m0*N + n;
                const float* x1 = xres + (size_t)(m0+8)*N + n;
                float* c0 = C + (size_t)m0*N + n;
                float* c1 = C + (size_t)(m0+8)*N + n;
                c0[0] = x0[0] + g0*v00; c0[1] = x0[1] + g1*v01;
                c1[0] = x1[0] + g0*v10; c1[1] = x1[1] + g1*v11;
            }
        }
    }
}

// ---------------- qkv split: rmsnorm q/k + rope -> fp16 (fp16 input) ----------------
__global__ void qkv_norm_rope_kernel(const __half* __restrict__ lin1h,
                                     const float* __restrict__ qn_w, const float* __restrict__ kn_w,
                                     const float* __restrict__ cosT, const float* __restrict__ sinT,
                                     __half* __restrict__ qo, __half* __restrict__ ko,
                                     __half* __restrict__ vo) {
    int t = blockIdx.x, h = blockIdx.y, d = threadIdx.x;
    const __half* base = lin1h + (size_t)t*(3*HIDN) + h*DH;
    float q = __half2float(base[d]);
    float k = __half2float(base[HIDN + d]);
    __half v = base[2*HIDN + d];
    float s1 = q*q, s2 = k*k;
#pragma unroll
    for (int o = 16; o > 0; o >>= 1) {
        s1 += __shfl_down_sync(0xffffffffu, s1, o);
        s2 += __shfl_down_sync(0xffffffffu, s2, o);
    }
    __shared__ float red[8];
    int wid = d >> 5, lid = d & 31;
    if (lid == 0) { red[wid] = s1; red[4+wid] = s2; }
    __syncthreads();
    float qs = rsqrtf((red[0]+red[1]+red[2]+red[3]) * (1.f/DH) + 1e-6f);
    float ks = rsqrtf((red[4]+red[5]+red[6]+red[7]) * (1.f/DH) + 1e-6f);
    q = q * qs * qn_w[d];
    k = k * ks * kn_w[d];
    __shared__ float sq[DH], sk[DH];
    sq[d] = q; sk[d] = k;
    __syncthreads();
    if (t < IMGN) {
        int i = d >> 1;
        float c = cosT[t*(DH/2) + i], s = sinT[t*(DH/2) + i];
        float x1 = sq[2*i], x2 = sq[2*i+1];
        q = (d & 1) ? (x1*s + x2*c) : (x1*c - x2*s);
        x1 = sk[2*i]; x2 = sk[2*i+1];
        k = (d & 1) ? (x1*s + x2*c) : (x1*c - x2*s);
    }
    size_t o = ((size_t)t*NH + h)*DH + d;
    qo[o] = __float2half_rn(q);
    ko[o] = __float2half_rn(k);
    vo[o] = v;
}

__global__ void ref_norm_rope_kernel(const float* __restrict__ rk, const float* __restrict__ w,
                                     const float* __restrict__ cosT, const float* __restrict__ sinT,
                                     __half* __restrict__ out) {
    int t = blockIdx.x, h = blockIdx.y, d = threadIdx.x;
    const float* base = rk + (size_t)t*HIDN + h*DH;
    float kv = base[d];
    float s = kv*kv;
#pragma unroll
    for (int o = 16; o > 0; o >>= 1) s += __shfl_down_sync(0xffffffffu, s, o);
    __shared__ float red[4];
    int wid = d >> 5, lid = d & 31;
    if (lid == 0) red[wid] = s;
    __syncthreads();
    float kn = kv * rsqrtf((red[0]+red[1]+red[2]+red[3]) * (1.f/DH) + 1e-6f) * w[d];
    __shared__ float sk[DH];
    sk[d] = kn;
    __syncthreads();
    int i = d >> 1;
    float c = cosT[t*(DH/2) + i], sn = sinT[t*(DH/2) + i];
    float x1 = sk[2*i], x2 = sk[2*i+1];
    float r = (d & 1) ? (x1*sn + x2*c) : (x1*c - x2*sn);
    out[(size_t)t*HIDN + h*DH + d] = __float2half_rn(r);
}

// ---------------- fused dual flash attention (self + IP, fp16 cat output) ----------------
#define FAH_Q 0
#define FAH_K 32768
#define FAH_V 65536
#define FAH_SMEM 98304

__global__ void __launch_bounds__(256, 1) fa_dual_kernel(
    const __half* __restrict__ Q,
    const __half* __restrict__ K1, const __half* __restrict__ V1,
    const __half* __restrict__ K2, const __half* __restrict__ V2,
    __half* __restrict__ cat, int Lk1, int Lk2)
{
    extern __shared__ char smem[];
    uint32_t sb = smem_u32(smem);
    int tid = threadIdx.x, lane = tid & 31, wid = tid >> 5;
    int h = blockIdx.y;
    int q0 = blockIdx.x * 128;
    const float scale = 0.08838834764831845f;

    // Q tile load
#pragma unroll
    for (int qi = 0; qi < 8; qi++) {
        int idx = qi*256 + tid;
        int r = idx >> 4, ch = idx & 15;
        uint32_t ad = sb + FAH_Q + (ch>>3)*16384 + SMEM_SWIZZLE_128B((uint32_t)(r*128 + (ch&7)*16));
        cp16(ad, Q + (size_t)(q0+r)*HD + h*DH + ch*8);
    }
    CP_COMMIT();

    auto load_kv = [&](const __half* Kp, const __half* Vp, int s, int k0) {
        uint32_t kbs = sb + FAH_K + s*16384;
        uint32_t vbs = sb + FAH_V + s*16384;
#pragma unroll
        for (int qi = 0; qi < 4; qi++) {
            int idx = qi*256 + tid;
            int r = idx >> 4, ch = idx & 15;
            uint32_t off = (ch>>3)*8192 + SMEM_SWIZZLE_128B((uint32_t)(r*128 + (ch&7)*16));
            cp16(kbs + off, Kp + (size_t)(k0+r)*HD + h*DH + ch*8);
            cp16(vbs + off, Vp + (size_t)(k0+r)*HD + h*DH + ch*8);
        }
    };
    load_kv(K1, V1, 0, 0);
    CP_COMMIT();

    CP_WAIT1();     // Q complete (KV tile0 may still be in flight)
    __syncthreads();

    uint32_t qa[8][4];
    {
        int row = wid*16 + (lane & 7) + ((lane >> 3) & 1)*8;
#pragma unroll
        for (int kc = 0; kc < 8; kc++) {
            int d = kc*16 + ((lane >> 4) & 1)*8;
            uint32_t ad = sb + FAH_Q + (d>>6)*16384 + SMEM_SWIZZLE_128B((uint32_t)(row*128 + (d&63)*2));
            ldsm4(qa[kc], ad);
        }
    }

    float o[16][4];
    float m0, m1, l0, l1;
    uint32_t o1p[16][2];   // phase-1 result, packed fp16

    for (int phase = 0; phase < 2; phase++) {
        const __half* Kp = phase ? K2 : K1;
        const __half* Vp = phase ? V2 : V1;
        int Lk = phase ? Lk2 : Lk1;
#pragma unroll
        for (int i = 0; i < 16; i++)
#pragma unroll
            for (int j = 0; j < 4; j++) o[i][j] = 0.f;
        m0 = -1e30f; m1 = -1e30f; l0 = 0.f; l1 = 0.f;

        if (phase == 1) { load_kv(Kp, Vp, 0, 0); CP_COMMIT(); }

        int T = Lk >> 6;
        for (int t = 0; t < T; t++) {
            if (t + 1 < T) { load_kv(Kp, Vp, (t+1) & 1, (t+1) << 6); CP_COMMIT(); CP_WAIT1(); }
            else           { CP_WAIT0(); }
            __syncthreads();
            uint32_t kst = sb + FAH_K + (t & 1)*16384;
            uint32_t vst = sb + FAH_V + (t & 1)*16384;

            float c[8][4];
#pragma unroll
            for (int i = 0; i < 8; i++)
#pragma unroll
                for (int j = 0; j < 4; j++) c[i][j] = 0.f;

            int krow = (lane & 7) + ((lane >> 4) & 1)*8;
            int kpl  = ((lane >> 3) & 1)*8;
#pragma unroll
            for (int nb2 = 0; nb2 < 4; nb2++) {
                int row = nb2*16 + krow;
#pragma unroll
                for (int kc = 0; kc < 8; kc++) {
                    uint32_t bf[4];
                    int d = kc*16 + kpl;
                    uint32_t ad = kst + (d>>6)*8192 + SMEM_SWIZZLE_128B((uint32_t)(row*128 + (d&63)*2));
                    ldsm4(bf, ad);
                    mma16816(c[nb2*2],   qa[kc], bf);
                    mma16816(c[nb2*2+1], qa[kc], bf + 2);
                }
            }

            float mn0 = m0, mn1 = m1;
#pragma unroll
            for (int nb = 0; nb < 8; nb++) {
                c[nb][0] *= scale; c[nb][1] *= scale; c[nb][2] *= scale; c[nb][3] *= scale;
                mn0 = fmaxf(mn0, fmaxf(c[nb][0], c[nb][1]));
                mn1 = fmaxf(mn1, fmaxf(c[nb][2], c[nb][3]));
            }
            mn0 = fmaxf(mn0, __shfl_xor_sync(0xffffffffu, mn0, 1));
            mn0 = fmaxf(mn0, __shfl_xor_sync(0xffffffffu, mn0, 2));
            mn1 = fmaxf(mn1, __shfl_xor_sync(0xffffffffu, mn1, 1));
            mn1 = fmaxf(mn1, __shfl_xor_sync(0xffffffffu, mn1, 2));
            float a0 = __expf(m0 - mn0), a1 = __expf(m1 - mn1);
            m0 = mn0; m1 = mn1;
            float s0 = 0.f, s1 = 0.f;
#pragma unroll
            for (int nb = 0; nb < 8; nb++) {
                c[nb][0] = __expf(c[nb][0] - m0);
                c[nb][1] = __expf(c[nb][1] - m0);
                c[nb][2] = __expf(c[nb][2] - m1);
                c[nb][3] = __expf(c[nb][3] - m1);
                s0 += c[nb][0] + c[nb][1];
                s1 += c[nb][2] + c[nb][3];
            }
            s0 += __shfl_xor_sync(0xffffffffu, s0, 1);
            s0 += __shfl_xor_sync(0xffffffffu, s0, 2);
            s1 += __shfl_xor_sync(0xffffffffu, s1, 1);
            s1 += __shfl_xor_sync(0xffffffffu, s1, 2);
            l0 = l0*a0 + s0;
            l1 = l1*a1 + s1;

#pragma unroll
            for (int nb = 0; nb < 16; nb++) {
                o[nb][0] *= a0; o[nb][1] *= a0; o[nb][2] *= a1; o[nb][3] *= a1;
            }

            uint32_t pa[4][4];
#pragma unroll
            for (int kc2 = 0; kc2 < 4; kc2++) {
                pa[kc2][0] = packh2(c[2*kc2][0],   c[2*kc2][1]);
                pa[kc2][1] = packh2(c[2*kc2][2],   c[2*kc2][3]);
                pa[kc2][2] = packh2(c[2*kc2+1][0], c[2*kc2+1][1]);
                pa[kc2][3] = packh2(c[2*kc2+1][2], c[2*kc2+1][3]);
            }

            int vrow = (lane & 7) + ((lane >> 3) & 1)*8;
            int npl  = ((lane >> 4) & 1)*8;
#pragma unroll
            for (int kc2 = 0; kc2 < 4; kc2++) {
                int row = kc2*16 + vrow;
#pragma unroll
                for (int nbp = 0; nbp < 8; nbp++) {
                    uint32_t bf[4];
                    int n = nbp*16 + npl;
                    uint32_t ad = vst + (n>>6)*8192 + SMEM_SWIZZLE_128B((uint32_t)(row*128 + (n&63)*2));
                    ldsm4t(bf, ad);
                    mma16816(o[nbp*2],   pa[kc2], bf);
                    mma16816(o[nbp*2+1], pa[kc2], bf + 2);
                }
            }
            __syncthreads();
        }

        if (phase == 0) {
            float inv0 = 1.f / l0, inv1 = 1.f / l1;
#pragma unroll
            for (int nb = 0; nb < 16; nb++) {
                o1p[nb][0] = packh2(o[nb][0]*inv0, o[nb][1]*inv0);
                o1p[nb][1] = packh2(o[nb][2]*inv1, o[nb][3]*inv1);
            }
        }
    }

    // epilogue: cat = O1 + O2
    float inv0 = 1.f / l0, inv1 = 1.f / l1;
    int r0 = q0 + wid*16 + (lane >> 2);
#pragma unroll
    for (int nb = 0; nb < 16; nb++) {
        int n = h*DH + nb*8 + (lane & 3)*2;
        float2 f0 = __half22float2(*(__half2*)&o1p[nb][0]);
        float2 f1 = __half22float2(*(__half2*)&o1p[nb][1]);
        uint32_t r0v = packh2(f0.x + o[nb][0]*inv0, f0.y + o[nb][1]*inv0);
        uint32_t r1v = packh2(f1.x + o[nb][2]*inv1, f1.y + o[nb][3]*inv1);
        *(uint32_t*)(cat + (size_t)r0*CATN + n)     = r0v;
        *(uint32_t*)(cat + (size_t)(r0+8)*CATN + n) = r1v;
    }
}

// ---------------- launcher ----------------
extern "C" void kernel_launch(void* const* d_in, const int* in_sizes, int n_in,
                              void* d_out, int out_size) {
    const float* x          = (const float*)d_in[0];
    const float* vec        = (const float*)d_in[1];
    const float* cosT       = (const float*)d_in[2];
    const float* sinT       = (const float*)d_in[3];
    const float* ref_latent = (const float*)d_in[4];
    const float* ref_cos    = (const float*)d_in[5];
    const float* ref_sin    = (const float*)d_in[6];
    const float* w_mod      = (const float*)d_in[7];
    const float* b_mod      = (const float*)d_in[8];
    const float* w1         = (const float*)d_in[9];
    const float* b1         = (const float*)d_in[10];
    const float* w2         = (const float*)d_in[11];
    const float* b2         = (const float*)d_in[12];
    const float* qn_w       = (const float*)d_in[13];
    const float* kn_w       = (const float*)d_in[14];
    const float* wk_ip      = (const float*)d_in[15];
    const float* bk_ip      = (const float*)d_in[16];
    const float* wv_ip      = (const float*)d_in[17];
    const float* bv_ip      = (const float*)d_in[18];
    const float* ref_kn_w   = (const float*)d_in[19];
    float* out = (float*)d_out;

    float *sv, *modb, *refk, *refv;
    __half *xb, *lin1h, *cat, *rlb, *qb, *kb, *vb, *refkb, *refvb;
    __half *w1b, *w2b, *wkb, *wvb;
    cudaGetSymbolAddress((void**)&sv,     g_sv);
    cudaGetSymbolAddress((void**)&modb,   g_mod);
    cudaGetSymbolAddress((void**)&xb,     g_xb);
    cudaGetSymbolAddress((void**)&lin1h,  g_lin1h);
    cudaGetSymbolAddress((void**)&qb,     g_qb);
    cudaGetSymbolAddress((void**)&kb,     g_kb);
    cudaGetSymbolAddress((void**)&vb,     g_vb);
    cudaGetSymbolAddress((void**)&cat,    g_cat);
    cudaGetSymbolAddress((void**)&refk,   g_refk);
    cudaGetSymbolAddress((void**)&refv,   g_refv);
    cudaGetSymbolAddress((void**)&refkb,  g_refkb);
    cudaGetSymbolAddress((void**)&refvb,  g_refvb);
    cudaGetSymbolAddress((void**)&rlb,    g_rlb);
    cudaGetSymbolAddress((void**)&w1b,    g_w1b);
    cudaGetSymbolAddress((void**)&w2b,    g_w2b);
    cudaGetSymbolAddress((void**)&wkb,    g_wkb);
    cudaGetSymbolAddress((void**)&wvb,    g_wvb);

    cudaFuncSetAttribute(tc_gemm_kernel,
                         cudaFuncAttributeMaxDynamicSharedMemorySize, GK_SMEM_TOTAL);
    cudaFuncSetAttribute(fa_dual_kernel,
                         cudaFuncAttributeMaxDynamicSharedMemorySize, FAH_SMEM);

    static cudaStream_t s1 = nullptr, s2 = nullptr;
    static cudaEvent_t evRoot = nullptr, evW1 = nullptr, evRef = nullptr, evW2 = nullptr;
    if (!s1) {
        cudaStreamCreateWithFlags(&s1, cudaStreamNonBlocking);
        cudaStreamCreateWithFlags(&s2, cudaStreamNonBlocking);
        cudaEventCreateWithFlags(&evRoot, cudaEventDisableTiming);
        cudaEventCreateWithFlags(&evW1,   cudaEventDisableTiming);
        cudaEventCreateWithFlags(&evRef,  cudaEventDisableTiming);
        cudaEventCreateWithFlags(&evW2,   cudaEventDisableTiming);
    }

    dim3 tb(32, 8);

    // fork
    cudaEventRecord(evRoot, 0);
    cudaStreamWaitEvent(s1, evRoot, 0);
    cudaStreamWaitEvent(s2, evRoot, 0);

    // s1: w1 convert (feeds lin1 GEMM)
    wcvtT_kernel<<<dim3(L1N/32, HIDN/64), tb, 0, s1>>>(w1, w1b, HIDN, L1N);
    cudaEventRecord(evW1, s1);

    // s2: ref chain + w2 convert
    wcvtT_kernel<<<dim3(HIDN/32, HIDN/64), tb, 0, s2>>>(wk_ip, wkb, HIDN, HIDN);
    wcvtT_kernel<<<dim3(HIDN/32, HIDN/64), tb, 0, s2>>>(wv_ip, wvb, HIDN, HIDN);
    cvt_h_kernel<<<(REFN*HIDN + 255)/256, 256, 0, s2>>>(ref_latent, rlb, (size_t)REFN*HIDN);
    tc_gemm_kernel<<<(REFN/128)*(HIDN/256), 256, GK_SMEM_TOTAL, s2>>>(
        rlb, wkb, bk_ip, refk, nullptr, nullptr, nullptr, nullptr, REFN, HIDN, HIDN, REFN/128, 0);
    tc_gemm_kernel<<<(REFN/128)*(HIDN/256), 256, GK_SMEM_TOTAL, s2>>>(
        rlb, wvb, bv_ip, refv, nullptr, nullptr, nullptr, nullptr, REFN, HIDN, HIDN, REFN/128, 0);
    ref_norm_rope_kernel<<<dim3(REFN, NH), 128, 0, s2>>>(refk, ref_kn_w, ref_cos, ref_sin, refkb);
    cvt_h_kernel<<<(REFN*HIDN + 255)/256, 256, 0, s2>>>(refv, refvb, (size_t)REFN*HIDN);
    cudaEventRecord(evRef, s2);
    wcvtT_kernel<<<dim3(HIDN/32, CATN/64), tb, 0, s2>>>(w2, w2b, CATN, HIDN);
    cudaEventRecord(evW2, s2);

    // main stream: mod chain
    silu_kernel<<<12, 256>>>(vec, sv);
    modproj_kernel<<<(3*HIDN)/32, 256>>>(sv, w_mod, b_mod, modb);
    ln_mod_kernel<<<LTOT, 256>>>(x, modb, xb);

    // lin1 GEMM (qkv fp16 + gelu-cat fused)
    cudaStreamWaitEvent(0, evW1, 0);
    tc_gemm_kernel<<<(LTOT/128)*(L1N/256), 256, GK_SMEM_TOTAL>>>(
        xb, w1b, b1, nullptr, lin1h, cat, nullptr, nullptr, LTOT, L1N, HIDN, LTOT/128, 1);

    // qkv norm/rope
    qkv_norm_rope_kernel<<<dim3(LTOT, NH), 128>>>(lin1h, qn_w, kn_w, cosT, sinT, qb, kb, vb);

    // fused dual attention (self + IP) -> fp16 cat
    cudaStreamWaitEvent(0, evRef, 0);
    fa_dual_kernel<<<dim3(LTOT/128, NH), 256, FAH_SMEM>>>(
        qb, kb, vb, refkb, refvb, cat, LTOT, REFN);

    // out GEMM with fused gated residual
    cudaStreamWaitEvent(0, evW2, 0);
    tc_gemm_kernel<<<(LTOT/128)*(HIDN/256), 256, GK_SMEM_TOTAL>>>(
        cat, w2b, b2, out, nullptr, nullptr, x, modb + 2*HIDN, LTOT, HIDN, CATN, LTOT/128, 2);
}

// round 9
// speedup vs baseline: 1.1417x; 1.1417x over previous
#include <cuda_runtime.h>
#include <cuda_fp16.h>
#include <cstdint>
#include <math.h>

// ---------------- problem constants ----------------
#define LTOT 2304      // IMG + TXT
#define IMGN 2048
#define TXTN 256
#define HIDN 3072
#define NH   24
#define DH   128
#define MLPN 12288
#define REFN 512
#define CATN (HIDN + MLPN)        // 15360
#define L1N  (3*HIDN + MLPN)      // 21504
#define HD   (NH*DH)              // 3072

// ---------------- helpers ----------------
__device__ __forceinline__ uint32_t smem_u32(const void* p) {
    uint32_t a;
    asm("{ .reg .u64 t; cvta.to.shared.u64 t, %1; cvt.u32.u64 %0, t; }" : "=r"(a) : "l"(p));
    return a;
}
#define SMEM_SWIZZLE_128B(byte_offset) ((byte_offset) ^ (((byte_offset) >> 3) & 0x70))

__device__ __forceinline__ void cp16(uint32_t saddr, const void* g) {
    asm volatile("cp.async.cg.shared.global [%0], [%1], 16;" :: "r"(saddr), "l"(g));
}
#define CP_COMMIT() asm volatile("cp.async.commit_group;" ::: "memory")
#define CP_WAIT1()  asm volatile("cp.async.wait_group 1;" ::: "memory")
#define CP_WAIT0()  asm volatile("cp.async.wait_group 0;" ::: "memory")

__device__ __forceinline__ void ldsm4(uint32_t r[4], uint32_t addr) {
    asm volatile("ldmatrix.sync.aligned.m8n8.x4.shared.b16 {%0,%1,%2,%3}, [%4];"
        : "=r"(r[0]), "=r"(r[1]), "=r"(r[2]), "=r"(r[3]) : "r"(addr));
}
__device__ __forceinline__ void ldsm4t(uint32_t r[4], uint32_t addr) {
    asm volatile("ldmatrix.sync.aligned.m8n8.x4.trans.shared.b16 {%0,%1,%2,%3}, [%4];"
        : "=r"(r[0]), "=r"(r[1]), "=r"(r[2]), "=r"(r[3]) : "r"(addr));
}
__device__ __forceinline__ void mma16816(float c[4], const uint32_t a[4], const uint32_t b[2]) {
    asm volatile("mma.sync.aligned.m16n8k16.row.col.f32.f16.f16.f32 "
        "{%0,%1,%2,%3}, {%4,%5,%6,%7}, {%8,%9}, {%0,%1,%2,%3};"
        : "+f"(c[0]), "+f"(c[1]), "+f"(c[2]), "+f"(c[3])
        : "r"(a[0]), "r"(a[1]), "r"(a[2]), "r"(a[3]), "r"(b[0]), "r"(b[1]));
}
__device__ __forceinline__ uint32_t packh2(float a, float b) {
    __half2 t = __floats2half2_rn(a, b);
    return *(uint32_t*)&t;
}
__device__ __forceinline__ float gelu_f(float x) {
    return 0.5f*x*(1.f + tanhf(0.7978845608028654f*(x + 0.044715f*x*x*x)));
}

// ---------------- device scratch ----------------
__device__ float g_sv[HIDN];
__device__ float g_mod[3*HIDN];
__device__ __half g_xb[(size_t)LTOT*HIDN];
__device__ __half g_lin1h[(size_t)LTOT*(3*HIDN)];    // qkv part, fp16
__device__ __half g_qb[(size_t)LTOT*HIDN];
__device__ __half g_kb[(size_t)LTOT*HIDN];
__device__ __half g_vb[(size_t)LTOT*HIDN];
__device__ __half g_cat[(size_t)LTOT*CATN];
__device__ float g_refk[(size_t)REFN*HIDN];
__device__ float g_refv[(size_t)REFN*HIDN];
__device__ __half g_refkb[(size_t)REFN*HIDN];
__device__ __half g_refvb[(size_t)REFN*HIDN];
__device__ __half g_rlb[(size_t)REFN*HIDN];
__device__ __half g_w1b[(size_t)L1N*HIDN];
__device__ __half g_w2b[(size_t)HIDN*CATN];
__device__ __half g_wkb[(size_t)HIDN*HIDN];
__device__ __half g_wvb[(size_t)HIDN*HIDN];

// ---------------- small kernels ----------------
__global__ void silu_kernel(const float* __restrict__ v, float* __restrict__ sv) {
    int i = blockIdx.x*blockDim.x + threadIdx.x;
    if (i < HIDN) { float x = v[i]; sv[i] = x / (1.f + __expf(-x)); }
}

__global__ void modproj_kernel(const float* __restrict__ sv, const float* __restrict__ w,
                               const float* __restrict__ b, float* __restrict__ mod) {
    __shared__ float red[8][32];
    int nx = threadIdx.x & 31, ky = threadIdx.x >> 5;
    int n = blockIdx.x*32 + nx;
    float acc = 0.f;
    for (int k = ky; k < HIDN; k += 8)
        acc = fmaf(sv[k], w[(size_t)k*(3*HIDN) + n], acc);
    red[ky][nx] = acc;
    __syncthreads();
    if (ky == 0) {
        float s = acc;
#pragma unroll
        for (int i = 1; i < 8; i++) s += red[i][nx];
        mod[n] = s + b[n];
    }
}

__global__ void ln_mod_kernel(const float* __restrict__ x, const float* __restrict__ mod,
                              __half* __restrict__ xb) {
    int row = blockIdx.x;
    int tid = threadIdx.x;
    const float* xr = x + (size_t)row*HIDN;
    float s = 0.f, s2 = 0.f;
    for (int i = tid; i < HIDN; i += 256) { float v = xr[i]; s += v; s2 += v*v; }
    __shared__ float rs[256], rs2[256];
    rs[tid] = s; rs2[tid] = s2; __syncthreads();
    for (int o = 128; o > 0; o >>= 1) {
        if (tid < o) { rs[tid] += rs[tid+o]; rs2[tid] += rs2[tid+o]; }
        __syncthreads();
    }
    float mean = rs[0] * (1.f/HIDN);
    float var  = rs2[0] * (1.f/HIDN) - mean*mean;
    float inv  = rsqrtf(var + 1e-6f);
    for (int i = tid; i < HIDN; i += 256) {
        float v = (xr[i] - mean) * inv;
        v = v * (1.f + mod[HIDN + i]) + mod[i];
        xb[(size_t)row*HIDN + i] = __float2half_rn(v);
    }
}

// transpose + convert: w[K,N] fp32 -> [N,K] fp16
__global__ void wcvtT_kernel(const float* __restrict__ w, __half* __restrict__ o,
                             int K, int N) {
    __shared__ __half t[32][66];
    int n0 = blockIdx.x*32, k0 = blockIdx.y*64;
    int tx = threadIdx.x, ty = threadIdx.y;  // 32 x 8
#pragma unroll
    for (int i = 0; i < 8; i++) {
        int k = ty + i*8;
        t[tx][k] = __float2half_rn(w[(size_t)(k0+k)*N + n0 + tx]);
    }
    __syncthreads();
#pragma unroll
    for (int i = 0; i < 4; i++) {
        int n = i*8 + ty;
        __half2 v = *(__half2*)&t[n][2*tx];
        *(__half2*)&o[(size_t)(n0+n)*K + k0 + 2*tx] = v;
    }
}

__global__ void cvt_h_kernel(const float* __restrict__ src, __half* __restrict__ dst,
                             size_t n) {
    size_t i = (size_t)blockIdx.x*blockDim.x + threadIdx.x;
    if (i < n) dst[i] = __float2half_rn(src[i]);
}

// ---------------- HMMA fp16 GEMM (round-7 tile: 128x128, 64x32 warps, 2 CTAs/SM) ----------------
// C[M,N] = A[M,K] @ B[N,K]^T + bias
// mode 0 (PLAIN): C fp32 stride N
// mode 1 (LIN1):  cols < 3*HIDN -> lin1h fp16 (stride 3*HIDN); cols >= -> gelu fp16 into cat
// mode 2 (OUT):   C = xres + gate[n]*(acc+bias), fp32, stride N
#define GS_B     16384
#define GS_STAGE 32768
#define GK_SMEM_TOTAL (2*GS_STAGE)

__global__ void __launch_bounds__(256, 2) tc_gemm_kernel(
    const __half* __restrict__ A, const __half* __restrict__ B,
    const float* __restrict__ bias, float* __restrict__ C,
    __half* __restrict__ lin1h, __half* __restrict__ cat,
    const float* __restrict__ xres, const float* __restrict__ gate,
    int M, int N, int K, int m_tiles, int mode)
{
    extern __shared__ char smem[];
    uint32_t sb = smem_u32(smem);
    int tid = threadIdx.x;
    int lane = tid & 31, wid = tid >> 5;
    int wm = wid >> 2, wn = wid & 3;   // warp tile: rows wm*64, cols wn*32

    int mi = blockIdx.x % m_tiles;
    int ni = blockIdx.x / m_tiles;
    int bm = mi * 128, bn = ni * 128;

    float acc[4][4][4];
#pragma unroll
    for (int i = 0; i < 4; i++)
#pragma unroll
        for (int j = 0; j < 4; j++)
#pragma unroll
            for (int r = 0; r < 4; r++) acc[i][j][r] = 0.f;

    int NC = K >> 6;

    auto load_stage = [&](int st, int k0) {
        uint32_t base = sb + st*GS_STAGE;
#pragma unroll
        for (int q = 0; q < 4; q++) {
            int idx = q*256 + tid;
            int r = idx >> 3;
            int ch = (idx & 7) << 4;
            uint32_t sw = SMEM_SWIZZLE_128B((uint32_t)(r*128 + ch));
            cp16(base + sw,        (const char*)(A + (size_t)(bm + r)*K + k0) + ch);
            cp16(base + GS_B + sw, (const char*)(B + (size_t)(bn + r)*K + k0) + ch);
        }
    };

    load_stage(0, 0);
    CP_COMMIT();

    for (int c = 0; c < NC; c++) {
        if (c + 1 < NC) { load_stage((c+1) & 1, (c+1) << 6); CP_COMMIT(); CP_WAIT1(); }
        else            { CP_WAIT0(); }
        __syncthreads();

        uint32_t base = sb + (c & 1)*GS_STAGE;
        int arow = wm*64 + (lane & 15);
        int apl  = ((lane >> 4) & 1) << 4;
        int brow = wn*32 + ((lane >> 4) & 1)*8 + (lane & 7);
        int bpl  = ((lane >> 3) & 1) << 4;
#pragma unroll
        for (int kk = 0; kk < 4; kk++) {
            uint32_t a[4][4], b[2][4];
#pragma unroll
            for (int i = 0; i < 4; i++) {
                uint32_t sw = SMEM_SWIZZLE_128B((uint32_t)((arow + i*16)*128 + kk*32 + apl));
                ldsm4(a[i], base + sw);
            }
#pragma unroll
            for (int jp = 0; jp < 2; jp++) {
                uint32_t sw = SMEM_SWIZZLE_128B((uint32_t)((brow + jp*16)*128 + kk*32 + bpl));
                ldsm4(b[jp], base + GS_B + sw);
            }
#pragma unroll
            for (int i = 0; i < 4; i++) {
                mma16816(acc[i][0], a[i], b[0]);
                mma16816(acc[i][1], a[i], b[0] + 2);
                mma16816(acc[i][2], a[i], b[1]);
                mma16816(acc[i][3], a[i], b[1] + 2);
            }
        }
        __syncthreads();
    }

#pragma unroll
    for (int i = 0; i < 4; i++) {
        int m0 = bm + wm*64 + i*16 + (lane >> 2);
#pragma unroll
        for (int j = 0; j < 4; j++) {
            int n = bn + wn*32 + j*8 + (lane & 3)*2;
            float b0 = bias[n], b1 = bias[n+1];
            float v00 = acc[i][j][0] + b0, v01 = acc[i][j][1] + b1;
            float v10 = acc[i][j][2] + b0, v11 = acc[i][j][3] + b1;
            if (mode == 0) {
                float* c0 = C + (size_t)m0*N + n;
                float* c1 = C + (size_t)(m0+8)*N + n;
                c0[0] = v00; c0[1] = v01; c1[0] = v10; c1[1] = v11;
            } else if (mode == 1) {
                if (bn < 3*HIDN) {
                    uint32_t p0 = packh2(v00, v01);
                    uint32_t p1 = packh2(v10, v11);
                    *(uint32_t*)(lin1h + (size_t)m0*(3*HIDN) + n)     = p0;
                    *(uint32_t*)(lin1h + (size_t)(m0+8)*(3*HIDN) + n) = p1;
                } else {
                    int nc = HIDN + (n - 3*HIDN);
                    uint32_t g0 = packh2(gelu_f(v00), gelu_f(v01));
                    uint32_t g1 = packh2(gelu_f(v10), gelu_f(v11));
                    *(uint32_t*)(cat + (size_t)m0*CATN + nc)     = g0;
                    *(uint32_t*)(cat + (size_t)(m0+8)*CATN + nc) = g1;
                }
            } else {
                float g0 = gate[n], g1 = gate[n+1];
                const float* x0 = xres + (size_t)m0*N + n;
                const float* x1 = xres + (size_t)(m0+8)*N + n;
                float* c0 = C + (size_t)m0*N + n;
                float* c1 = C + (size_t)(m0+8)*N + n;
                c0[0] = x0[0] + g0*v00; c0[1] = x0[1] + g1*v01;
                c1[0] = x1[0] + g0*v10; c1[1] = x1[1] + g1*v11;
            }
        }
    }
}

// ---------------- qkv split: rmsnorm q/k + rope -> fp16 (fp16 input) ----------------
__global__ void qkv_norm_rope_kernel(const __half* __restrict__ lin1h,
                                     const float* __restrict__ qn_w, const float* __restrict__ kn_w,
                                     const float* __restrict__ cosT, const float* __restrict__ sinT,
                                     __half* __restrict__ qo, __half* __restrict__ ko,
                                     __half* __restrict__ vo) {
    int t = blockIdx.x, h = blockIdx.y, d = threadIdx.x;
    const __half* base = lin1h + (size_t)t*(3*HIDN) + h*DH;
    float q = __half2float(base[d]);
    float k = __half2float(base[HIDN + d]);
    __half v = base[2*HIDN + d];
    float s1 = q*q, s2 = k*k;
#pragma unroll
    for (int o = 16; o > 0; o >>= 1) {
        s1 += __shfl_down_sync(0xffffffffu, s1, o);
        s2 += __shfl_down_sync(0xffffffffu, s2, o);
    }
    __shared__ float red[8];
    int wid = d >> 5, lid = d & 31;
    if (lid == 0) { red[wid] = s1; red[4+wid] = s2; }
    __syncthreads();
    float qs = rsqrtf((red[0]+red[1]+red[2]+red[3]) * (1.f/DH) + 1e-6f);
    float ks = rsqrtf((red[4]+red[5]+red[6]+red[7]) * (1.f/DH) + 1e-6f);
    q = q * qs * qn_w[d];
    k = k * ks * kn_w[d];
    __shared__ float sq[DH], sk[DH];
    sq[d] = q; sk[d] = k;
    __syncthreads();
    if (t < IMGN) {
        int i = d >> 1;
        float c = cosT[t*(DH/2) + i], s = sinT[t*(DH/2) + i];
        float x1 = sq[2*i], x2 = sq[2*i+1];
        q = (d & 1) ? (x1*s + x2*c) : (x1*c - x2*s);
        x1 = sk[2*i]; x2 = sk[2*i+1];
        k = (d & 1) ? (x1*s + x2*c) : (x1*c - x2*s);
    }
    size_t o = ((size_t)t*NH + h)*DH + d;
    qo[o] = __float2half_rn(q);
    ko[o] = __float2half_rn(k);
    vo[o] = v;
}

__global__ void ref_norm_rope_kernel(const float* __restrict__ rk, const float* __restrict__ w,
                                     const float* __restrict__ cosT, const float* __restrict__ sinT,
                                     __half* __restrict__ out) {
    int t = blockIdx.x, h = blockIdx.y, d = threadIdx.x;
    const float* base = rk + (size_t)t*HIDN + h*DH;
    float kv = base[d];
    float s = kv*kv;
#pragma unroll
    for (int o = 16; o > 0; o >>= 1) s += __shfl_down_sync(0xffffffffu, s, o);
    __shared__ float red[4];
    int wid = d >> 5, lid = d & 31;
    if (lid == 0) red[wid] = s;
    __syncthreads();
    float kn = kv * rsqrtf((red[0]+red[1]+red[2]+red[3]) * (1.f/DH) + 1e-6f) * w[d];
    __shared__ float sk[DH];
    sk[d] = kn;
    __syncthreads();
    int i = d >> 1;
    float c = cosT[t*(DH/2) + i], sn = sinT[t*(DH/2) + i];
    float x1 = sk[2*i], x2 = sk[2*i+1];
    float r = (d & 1) ? (x1*sn + x2*c) : (x1*c - x2*sn);
    out[(size_t)t*HIDN + h*DH + d] = __float2half_rn(r);
}

// ---------------- fused dual flash attention (self + IP, fp16 cat output) ----------------
#define FAH_Q 0
#define FAH_K 32768
#define FAH_V 65536
#define FAH_SMEM 98304

__global__ void __launch_bounds__(256, 1) fa_dual_kernel(
    const __half* __restrict__ Q,
    const __half* __restrict__ K1, const __half* __restrict__ V1,
    const __half* __restrict__ K2, const __half* __restrict__ V2,
    __half* __restrict__ cat, int Lk1, int Lk2)
{
    extern __shared__ char smem[];
    uint32_t sb = smem_u32(smem);
    int tid = threadIdx.x, lane = tid & 31, wid = tid >> 5;
    int h = blockIdx.y;
    int q0 = blockIdx.x * 128;
    const float scale = 0.08838834764831845f;

#pragma unroll
    for (int qi = 0; qi < 8; qi++) {
        int idx = qi*256 + tid;
        int r = idx >> 4, ch = idx & 15;
        uint32_t ad = sb + FAH_Q + (ch>>3)*16384 + SMEM_SWIZZLE_128B((uint32_t)(r*128 + (ch&7)*16));
        cp16(ad, Q + (size_t)(q0+r)*HD + h*DH + ch*8);
    }
    CP_COMMIT();

    auto load_kv = [&](const __half* Kp, const __half* Vp, int s, int k0) {
        uint32_t kbs = sb + FAH_K + s*16384;
        uint32_t vbs = sb + FAH_V + s*16384;
#pragma unroll
        for (int qi = 0; qi < 4; qi++) {
            int idx = qi*256 + tid;
            int r = idx >> 4, ch = idx & 15;
            uint32_t off = (ch>>3)*8192 + SMEM_SWIZZLE_128B((uint32_t)(r*128 + (ch&7)*16));
            cp16(kbs + off, Kp + (size_t)(k0+r)*HD + h*DH + ch*8);
            cp16(vbs + off, Vp + (size_t)(k0+r)*HD + h*DH + ch*8);
        }
    };
    load_kv(K1, V1, 0, 0);
    CP_COMMIT();

    CP_WAIT1();
    __syncthreads();

    uint32_t qa[8][4];
    {
        int row = wid*16 + (lane & 7) + ((lane >> 3) & 1)*8;
#pragma unroll
        for (int kc = 0; kc < 8; kc++) {
            int d = kc*16 + ((lane >> 4) & 1)*8;
            uint32_t ad = sb + FAH_Q + (d>>6)*16384 + SMEM_SWIZZLE_128B((uint32_t)(row*128 + (d&63)*2));
            ldsm4(qa[kc], ad);
        }
    }

    float o[16][4];
    float m0, m1, l0, l1;
    uint32_t o1p[16][2];

    for (int phase = 0; phase < 2; phase++) {
        const __half* Kp = phase ? K2 : K1;
        const __half* Vp = phase ? V2 : V1;
        int Lk = phase ? Lk2 : Lk1;
#pragma unroll
        for (int i = 0; i < 16; i++)
#pragma unroll
            for (int j = 0; j < 4; j++) o[i][j] = 0.f;
        m0 = -1e30f; m1 = -1e30f; l0 = 0.f; l1 = 0.f;

        if (phase == 1) { load_kv(Kp, Vp, 0, 0); CP_COMMIT(); }

        int T = Lk >> 6;
        for (int t = 0; t < T; t++) {
            if (t + 1 < T) { load_kv(Kp, Vp, (t+1) & 1, (t+1) << 6); CP_COMMIT(); CP_WAIT1(); }
            else           { CP_WAIT0(); }
            __syncthreads();
            uint32_t kst = sb + FAH_K + (t & 1)*16384;
            uint32_t vst = sb + FAH_V + (t & 1)*16384;

            float c[8][4];
#pragma unroll
            for (int i = 0; i < 8; i++)
#pragma unroll
                for (int j = 0; j < 4; j++) c[i][j] = 0.f;

            int krow = (lane & 7) + ((lane >> 4) & 1)*8;
            int kpl  = ((lane >> 3) & 1)*8;
#pragma unroll
            for (int nb2 = 0; nb2 < 4; nb2++) {
                int row = nb2*16 + krow;
#pragma unroll
                for (int kc = 0; kc < 8; kc++) {
                    uint32_t bf[4];
                    int d = kc*16 + kpl;
                    uint32_t ad = kst + (d>>6)*8192 + SMEM_SWIZZLE_128B((uint32_t)(row*128 + (d&63)*2));
                    ldsm4(bf, ad);
                    mma16816(c[nb2*2],   qa[kc], bf);
                    mma16816(c[nb2*2+1], qa[kc], bf + 2);
                }
            }

            float mn0 = m0, mn1 = m1;
#pragma unroll
            for (int nb = 0; nb < 8; nb++) {
                c[nb][0] *= scale; c[nb][1] *= scale; c[nb][2] *= scale; c[nb][3] *= scale;
                mn0 = fmaxf(mn0, fmaxf(c[nb][0], c[nb][1]));
                mn1 = fmaxf(mn1, fmaxf(c[nb][2], c[nb][3]));
            }
            mn0 = fmaxf(mn0, __shfl_xor_sync(0xffffffffu, mn0, 1));
            mn0 = fmaxf(mn0, __shfl_xor_sync(0xffffffffu, mn0, 2));
            mn1 = fmaxf(mn1, __shfl_xor_sync(0xffffffffu, mn1, 1));
            mn1 = fmaxf(mn1, __shfl_xor_sync(0xffffffffu, mn1, 2));
            float a0 = __expf(m0 - mn0), a1 = __expf(m1 - mn1);
            m0 = mn0; m1 = mn1;
            float s0 = 0.f, s1 = 0.f;
#pragma unroll
            for (int nb = 0; nb < 8; nb++) {
                c[nb][0] = __expf(c[nb][0] - m0);
                c[nb][1] = __expf(c[nb][1] - m0);
                c[nb][2] = __expf(c[nb][2] - m1);
                c[nb][3] = __expf(c[nb][3] - m1);
                s0 += c[nb][0] + c[nb][1];
                s1 += c[nb][2] + c[nb][3];
            }
            s0 += __shfl_xor_sync(0xffffffffu, s0, 1);
            s0 += __shfl_xor_sync(0xffffffffu, s0, 2);
            s1 += __shfl_xor_sync(0xffffffffu, s1, 1);
            s1 += __shfl_xor_sync(0xffffffffu, s1, 2);
            l0 = l0*a0 + s0;
            l1 = l1*a1 + s1;

#pragma unroll
            for (int nb = 0; nb < 16; nb++) {
                o[nb][0] *= a0; o[nb][1] *= a0; o[nb][2] *= a1; o[nb][3] *= a1;
            }

            uint32_t pa[4][4];
#pragma unroll
            for (int kc2 = 0; kc2 < 4; kc2++) {
                pa[kc2][0] = packh2(c[2*kc2][0],   c[2*kc2][1]);
                pa[kc2][1] = packh2(c[2*kc2][2],   c[2*kc2][3]);
                pa[kc2][2] = packh2(c[2*kc2+1][0], c[2*kc2+1][1]);
                pa[kc2][3] = packh2(c[2*kc2+1][2], c[2*kc2+1][3]);
            }

            int vrow = (lane & 7) + ((lane >> 3) & 1)*8;
            int npl  = ((lane >> 4) & 1)*8;
#pragma unroll
            for (int kc2 = 0; kc2 < 4; kc2++) {
                int row = kc2*16 + vrow;
#pragma unroll
                for (int nbp = 0; nbp < 8; nbp++) {
                    uint32_t bf[4];
                    int n = nbp*16 + npl;
                    uint32_t ad = vst + (n>>6)*8192 + SMEM_SWIZZLE_128B((uint32_t)(row*128 + (n&63)*2));
                    ldsm4t(bf, ad);
                    mma16816(o[nbp*2],   pa[kc2], bf);
                    mma16816(o[nbp*2+1], pa[kc2], bf + 2);
                }
            }
            __syncthreads();
        }

        if (phase == 0) {
            float inv0 = 1.f / l0, inv1 = 1.f / l1;
#pragma unroll
            for (int nb = 0; nb < 16; nb++) {
                o1p[nb][0] = packh2(o[nb][0]*inv0, o[nb][1]*inv0);
                o1p[nb][1] = packh2(o[nb][2]*inv1, o[nb][3]*inv1);
            }
        }
    }

    float inv0 = 1.f / l0, inv1 = 1.f / l1;
    int r0 = q0 + wid*16 + (lane >> 2);
#pragma unroll
    for (int nb = 0; nb < 16; nb++) {
        int n = h*DH + nb*8 + (lane & 3)*2;
        float2 f0 = __half22float2(*(__half2*)&o1p[nb][0]);
        float2 f1 = __half22float2(*(__half2*)&o1p[nb][1]);
        uint32_t r0v = packh2(f0.x + o[nb][0]*inv0, f0.y + o[nb][1]*inv0);
        uint32_t r1v = packh2(f1.x + o[nb][2]*inv1, f1.y + o[nb][3]*inv1);
        *(uint32_t*)(cat + (size_t)r0*CATN + n)     = r0v;
        *(uint32_t*)(cat + (size_t)(r0+8)*CATN + n) = r1v;
    }
}

// ---------------- launcher ----------------
extern "C" void kernel_launch(void* const* d_in, const int* in_sizes, int n_in,
                              void* d_out, int out_size) {
    const float* x          = (const float*)d_in[0];
    const float* vec        = (const float*)d_in[1];
    const float* cosT       = (const float*)d_in[2];
    const float* sinT       = (const float*)d_in[3];
    const float* ref_latent = (const float*)d_in[4];
    const float* ref_cos    = (const float*)d_in[5];
    const float* ref_sin    = (const float*)d_in[6];
    const float* w_mod      = (const float*)d_in[7];
    const float* b_mod      = (const float*)d_in[8];
    const float* w1         = (const float*)d_in[9];
    const float* b1         = (const float*)d_in[10];
    const float* w2         = (const float*)d_in[11];
    const float* b2         = (const float*)d_in[12];
    const float* qn_w       = (const float*)d_in[13];
    const float* kn_w       = (const float*)d_in[14];
    const float* wk_ip      = (const float*)d_in[15];
    const float* bk_ip      = (const float*)d_in[16];
    const float* wv_ip      = (const float*)d_in[17];
    const float* bv_ip      = (const float*)d_in[18];
    const float* ref_kn_w   = (const float*)d_in[19];
    float* out = (float*)d_out;

    float *sv, *modb, *refk, *refv;
    __half *xb, *lin1h, *cat, *rlb, *qb, *kb, *vb, *refkb, *refvb;
    __half *w1b, *w2b, *wkb, *wvb;
    cudaGetSymbolAddress((void**)&sv,     g_sv);
    cudaGetSymbolAddress((void**)&modb,   g_mod);
    cudaGetSymbolAddress((void**)&xb,     g_xb);
    cudaGetSymbolAddress((void**)&lin1h,  g_lin1h);
    cudaGetSymbolAddress((void**)&qb,     g_qb);
    cudaGetSymbolAddress((void**)&kb,     g_kb);
    cudaGetSymbolAddress((void**)&vb,     g_vb);
    cudaGetSymbolAddress((void**)&cat,    g_cat);
    cudaGetSymbolAddress((void**)&refk,   g_refk);
    cudaGetSymbolAddress((void**)&refv,   g_refv);
    cudaGetSymbolAddress((void**)&refkb,  g_refkb);
    cudaGetSymbolAddress((void**)&refvb,  g_refvb);
    cudaGetSymbolAddress((void**)&rlb,    g_rlb);
    cudaGetSymbolAddress((void**)&w1b,    g_w1b);
    cudaGetSymbolAddress((void**)&w2b,    g_w2b);
    cudaGetSymbolAddress((void**)&wkb,    g_wkb);
    cudaGetSymbolAddress((void**)&wvb,    g_wvb);

    cudaFuncSetAttribute(tc_gemm_kernel,
                         cudaFuncAttributeMaxDynamicSharedMemorySize, GK_SMEM_TOTAL);
    cudaFuncSetAttribute(fa_dual_kernel,
                         cudaFuncAttributeMaxDynamicSharedMemorySize, FAH_SMEM);

    static cudaStream_t s1 = nullptr, s2 = nullptr;
    static cudaEvent_t evRoot = nullptr, evW1 = nullptr, evRef = nullptr, evW2 = nullptr;
    if (!s1) {
        cudaStreamCreateWithFlags(&s1, cudaStreamNonBlocking);
        cudaStreamCreateWithFlags(&s2, cudaStreamNonBlocking);
        cudaEventCreateWithFlags(&evRoot, cudaEventDisableTiming);
        cudaEventCreateWithFlags(&evW1,   cudaEventDisableTiming);
        cudaEventCreateWithFlags(&evRef,  cudaEventDisableTiming);
        cudaEventCreateWithFlags(&evW2,   cudaEventDisableTiming);
    }

    dim3 tb(32, 8);

    // fork
    cudaEventRecord(evRoot, 0);
    cudaStreamWaitEvent(s1, evRoot, 0);
    cudaStreamWaitEvent(s2, evRoot, 0);

    // s1: w1 convert (feeds lin1 GEMM)
    wcvtT_kernel<<<dim3(L1N/32, HIDN/64), tb, 0, s1>>>(w1, w1b, HIDN, L1N);
    cudaEventRecord(evW1, s1);

    // s2: ref chain + w2 convert
    wcvtT_kernel<<<dim3(HIDN/32, HIDN/64), tb, 0, s2>>>(wk_ip, wkb, HIDN, HIDN);
    wcvtT_kernel<<<dim3(HIDN/32, HIDN/64), tb, 0, s2>>>(wv_ip, wvb, HIDN, HIDN);
    cvt_h_kernel<<<(REFN*HIDN + 255)/256, 256, 0, s2>>>(ref_latent, rlb, (size_t)REFN*HIDN);
    tc_gemm_kernel<<<(REFN/128)*(HIDN/128), 256, GK_SMEM_TOTAL, s2>>>(
        rlb, wkb, bk_ip, refk, nullptr, nullptr, nullptr, nullptr, REFN, HIDN, HIDN, REFN/128, 0);
    tc_gemm_kernel<<<(REFN/128)*(HIDN/128), 256, GK_SMEM_TOTAL, s2>>>(
        rlb, wvb, bv_ip, refv, nullptr, nullptr, nullptr, nullptr, REFN, HIDN, HIDN, REFN/128, 0);
    ref_norm_rope_kernel<<<dim3(REFN, NH), 128, 0, s2>>>(refk, ref_kn_w, ref_cos, ref_sin, refkb);
    cvt_h_kernel<<<(REFN*HIDN + 255)/256, 256, 0, s2>>>(refv, refvb, (size_t)REFN*HIDN);
    cudaEventRecord(evRef, s2);
    wcvtT_kernel<<<dim3(HIDN/32, CATN/64), tb, 0, s2>>>(w2, w2b, CATN, HIDN);
    cudaEventRecord(evW2, s2);

    // main stream: mod chain
    silu_kernel<<<12, 256>>>(vec, sv);
    modproj_kernel<<<(3*HIDN)/32, 256>>>(sv, w_mod, b_mod, modb);
    ln_mod_kernel<<<LTOT, 256>>>(x, modb, xb);

    // lin1 GEMM (qkv fp16 + gelu-cat fused)
    cudaStreamWaitEvent(0, evW1, 0);
    tc_gemm_kernel<<<(LTOT/128)*(L1N/128), 256, GK_SMEM_TOTAL>>>(
        xb, w1b, b1, nullptr, lin1h, cat, nullptr, nullptr, LTOT, L1N, HIDN, LTOT/128, 1);

    // qkv norm/rope
    qkv_norm_rope_kernel<<<dim3(LTOT, NH), 128>>>(lin1h, qn_w, kn_w, cosT, sinT, qb, kb, vb);

    // fused dual attention (self + IP) -> fp16 cat
    cudaStreamWaitEvent(0, evRef, 0);
    fa_dual_kernel<<<dim3(LTOT/128, NH), 256, FAH_SMEM>>>(
        qb, kb, vb, refkb, refvb, cat, LTOT, REFN);

    // out GEMM with fused gated residual
    cudaStreamWaitEvent(0, evW2, 0);
    tc_gemm_kernel<<<(LTOT/128)*(HIDN/128), 256, GK_SMEM_TOTAL>>>(
        cat, w2b, b2, out, nullptr, nullptr, x, modb + 2*HIDN, LTOT, HIDN, CATN, LTOT/128, 2);
}

// round 10
// speedup vs baseline: 1.1472x; 1.0049x over previous
#include <cuda_runtime.h>
#include <cuda_fp16.h>
#include <cstdint>
#include <math.h>

// ---------------- problem constants ----------------
#define LTOT 2304      // IMG + TXT
#define IMGN 2048
#define TXTN 256
#define HIDN 3072
#define NH   24
#define DH   128
#define MLPN 12288
#define REFN 512
#define CATN (HIDN + MLPN)        // 15360
#define L1N  (3*HIDN + MLPN)      // 21504
#define HD   (NH*DH)              // 3072

// ---------------- helpers ----------------
__device__ __forceinline__ uint32_t smem_u32(const void* p) {
    uint32_t a;
    asm("{ .reg .u64 t; cvta.to.shared.u64 t, %1; cvt.u32.u64 %0, t; }" : "=r"(a) : "l"(p));
    return a;
}
#define SMEM_SWIZZLE_128B(byte_offset) ((byte_offset) ^ (((byte_offset) >> 3) & 0x70))

__device__ __forceinline__ void cp16(uint32_t saddr, const void* g) {
    asm volatile("cp.async.cg.shared.global [%0], [%1], 16;" :: "r"(saddr), "l"(g));
}
#define CP_COMMIT() asm volatile("cp.async.commit_group;" ::: "memory")
#define CP_WAIT1()  asm volatile("cp.async.wait_group 1;" ::: "memory")
#define CP_WAIT0()  asm volatile("cp.async.wait_group 0;" ::: "memory")

__device__ __forceinline__ void ldsm4(uint32_t r[4], uint32_t addr) {
    asm volatile("ldmatrix.sync.aligned.m8n8.x4.shared.b16 {%0,%1,%2,%3}, [%4];"
        : "=r"(r[0]), "=r"(r[1]), "=r"(r[2]), "=r"(r[3]) : "r"(addr));
}
__device__ __forceinline__ void ldsm4t(uint32_t r[4], uint32_t addr) {
    asm volatile("ldmatrix.sync.aligned.m8n8.x4.trans.shared.b16 {%0,%1,%2,%3}, [%4];"
        : "=r"(r[0]), "=r"(r[1]), "=r"(r[2]), "=r"(r[3]) : "r"(addr));
}
__device__ __forceinline__ void mma16816(float c[4], const uint32_t a[4], const uint32_t b[2]) {
    asm volatile("mma.sync.aligned.m16n8k16.row.col.f32.f16.f16.f32 "
        "{%0,%1,%2,%3}, {%4,%5,%6,%7}, {%8,%9}, {%0,%1,%2,%3};"
        : "+f"(c[0]), "+f"(c[1]), "+f"(c[2]), "+f"(c[3])
        : "r"(a[0]), "r"(a[1]), "r"(a[2]), "r"(a[3]), "r"(b[0]), "r"(b[1]));
}
__device__ __forceinline__ uint32_t packh2(float a, float b) {
    __half2 t = __floats2half2_rn(a, b);
    return *(uint32_t*)&t;
}
__device__ __forceinline__ float gelu_f(float x) {
    return 0.5f*x*(1.f + tanhf(0.7978845608028654f*(x + 0.044715f*x*x*x)));
}

// ---------------- device scratch ----------------
__device__ float g_sv[HIDN];
__device__ float g_mod[3*HIDN];
__device__ __half g_xb[(size_t)LTOT*HIDN];
__device__ __half g_lin1h[(size_t)LTOT*(3*HIDN)];
__device__ __half g_qb[(size_t)LTOT*HIDN];
__device__ __half g_kb[(size_t)LTOT*HIDN];
__device__ __half g_vb[(size_t)LTOT*HIDN];
__device__ __half g_cat[(size_t)LTOT*CATN];
__device__ float g_part[(size_t)2*LTOT*HIDN];        // split-K partials
__device__ float g_refk[(size_t)REFN*HIDN];
__device__ float g_refv[(size_t)REFN*HIDN];
__device__ __half g_refkb[(size_t)REFN*HIDN];
__device__ __half g_refvb[(size_t)REFN*HIDN];
__device__ __half g_rlb[(size_t)REFN*HIDN];
__device__ __half g_w1b[(size_t)L1N*HIDN];
__device__ __half g_w2b[(size_t)HIDN*CATN];
__device__ __half g_wkb[(size_t)HIDN*HIDN];
__device__ __half g_wvb[(size_t)HIDN*HIDN];

// ---------------- small kernels ----------------
__global__ void silu_kernel(const float* __restrict__ v, float* __restrict__ sv) {
    int i = blockIdx.x*blockDim.x + threadIdx.x;
    if (i < HIDN) { float x = v[i]; sv[i] = x / (1.f + __expf(-x)); }
}

__global__ void modproj_kernel(const float* __restrict__ sv, const float* __restrict__ w,
                               const float* __restrict__ b, float* __restrict__ mod) {
    __shared__ float red[8][32];
    int nx = threadIdx.x & 31, ky = threadIdx.x >> 5;
    int n = blockIdx.x*32 + nx;
    float acc = 0.f;
    for (int k = ky; k < HIDN; k += 8)
        acc = fmaf(sv[k], w[(size_t)k*(3*HIDN) + n], acc);
    red[ky][nx] = acc;
    __syncthreads();
    if (ky == 0) {
        float s = acc;
#pragma unroll
        for (int i = 1; i < 8; i++) s += red[i][nx];
        mod[n] = s + b[n];
    }
}

__global__ void ln_mod_kernel(const float* __restrict__ x, const float* __restrict__ mod,
                              __half* __restrict__ xb) {
    int row = blockIdx.x;
    int tid = threadIdx.x;
    const float* xr = x + (size_t)row*HIDN;
    float s = 0.f, s2 = 0.f;
    for (int i = tid; i < HIDN; i += 256) { float v = xr[i]; s += v; s2 += v*v; }
    __shared__ float rs[256], rs2[256];
    rs[tid] = s; rs2[tid] = s2; __syncthreads();
    for (int o = 128; o > 0; o >>= 1) {
        if (tid < o) { rs[tid] += rs[tid+o]; rs2[tid] += rs2[tid+o]; }
        __syncthreads();
    }
    float mean = rs[0] * (1.f/HIDN);
    float var  = rs2[0] * (1.f/HIDN) - mean*mean;
    float inv  = rsqrtf(var + 1e-6f);
    for (int i = tid; i < HIDN; i += 256) {
        float v = (xr[i] - mean) * inv;
        v = v * (1.f + mod[HIDN + i]) + mod[i];
        xb[(size_t)row*HIDN + i] = __float2half_rn(v);
    }
}

// transpose + convert: w[K,N] fp32 -> [N,K] fp16
__global__ void wcvtT_kernel(const float* __restrict__ w, __half* __restrict__ o,
                             int K, int N) {
    __shared__ __half t[32][66];
    int n0 = blockIdx.x*32, k0 = blockIdx.y*64;
    int tx = threadIdx.x, ty = threadIdx.y;  // 32 x 8
#pragma unroll
    for (int i = 0; i < 8; i++) {
        int k = ty + i*8;
        t[tx][k] = __float2half_rn(w[(size_t)(k0+k)*N + n0 + tx]);
    }
    __syncthreads();
#pragma unroll
    for (int i = 0; i < 4; i++) {
        int n = i*8 + ty;
        __half2 v = *(__half2*)&t[n][2*tx];
        *(__half2*)&o[(size_t)(n0+n)*K + k0 + 2*tx] = v;
    }
}

__global__ void cvt_h_kernel(const float* __restrict__ src, __half* __restrict__ dst,
                             size_t n) {
    size_t i = (size_t)blockIdx.x*blockDim.x + threadIdx.x;
    if (i < n) dst[i] = __float2half_rn(src[i]);
}

// final: out = x + gate[col] * (p0 + p1 + bias[col]), float4-vectorized
__global__ void final_add_kernel(const float* __restrict__ x, const float* __restrict__ part,
                                 const float* __restrict__ bias, const float* __restrict__ gate,
                                 float* __restrict__ out) {
    int idx = (blockIdx.x*blockDim.x + threadIdx.x) * 4;   // element index
    int col = idx % HIDN;
    float4 xv = *(const float4*)(x + idx);
    float4 p0 = *(const float4*)(part + idx);
    float4 p1 = *(const float4*)(part + (size_t)LTOT*HIDN + idx);
    float4 bv = *(const float4*)(bias + col);
    float4 gv = *(const float4*)(gate + col);
    float4 r;
    r.x = xv.x + gv.x*(p0.x + p1.x + bv.x);
    r.y = xv.y + gv.y*(p0.y + p1.y + bv.y);
    r.z = xv.z + gv.z*(p0.z + p1.z + bv.z);
    r.w = xv.w + gv.w*(p0.w + p1.w + bv.w);
    *(float4*)(out + idx) = r;
}

// ---------------- HMMA fp16 GEMM: 128x128 tile, 64x32 warps, 3-stage pipeline ----------------
// C[M,N] = A[M,(lda)] @ B[N,(lda)]^T (+ bias), reduction span K starting at ks*K.
// mode 0 (PLAIN): C = acc + bias, fp32 stride N
// mode 1 (LIN1):  cols < 3*HIDN -> lin1h fp16; cols >= -> gelu fp16 into cat
// mode 3 (PART):  C + ks*M*N = acc (no bias), fp32 stride N   [split-K partials]
#define GS_B     16384
#define GS_STAGE 32768
#define GK_SMEM_TOTAL (3*GS_STAGE)

__global__ void __launch_bounds__(256, 2) tc_gemm_kernel(
    const __half* __restrict__ A, const __half* __restrict__ B,
    const float* __restrict__ bias, float* __restrict__ C,
    __half* __restrict__ lin1h, __half* __restrict__ cat,
    int M, int N, int K, int lda, int m_tiles, int mode)
{
    extern __shared__ char smem[];
    uint32_t sb = smem_u32(smem);
    int tid = threadIdx.x;
    int lane = tid & 31, wid = tid >> 5;
    int wm = wid >> 2, wn = wid & 3;

    int per = m_tiles * (N >> 7);
    int bid = blockIdx.x;
    int ks = bid / per;
    bid -= ks * per;
    int mi = bid % m_tiles;
    int ni = bid / m_tiles;
    int bm = mi * 128, bn = ni * 128;
    int kbase = ks * K;

    float acc[4][4][4];
#pragma unroll
    for (int i = 0; i < 4; i++)
#pragma unroll
        for (int j = 0; j < 4; j++)
#pragma unroll
            for (int r = 0; r < 4; r++) acc[i][j][r] = 0.f;

    int NC = K >> 6;

    auto load_stage = [&](int st, int k0) {
        uint32_t base = sb + st*GS_STAGE;
#pragma unroll
        for (int q = 0; q < 4; q++) {
            int idx = q*256 + tid;
            int r = idx >> 3;
            int ch = (idx & 7) << 4;
            uint32_t sw = SMEM_SWIZZLE_128B((uint32_t)(r*128 + ch));
            cp16(base + sw,        (const char*)(A + (size_t)(bm + r)*lda + kbase + k0) + ch);
            cp16(base + GS_B + sw, (const char*)(B + (size_t)(bn + r)*lda + kbase + k0) + ch);
        }
    };

    load_stage(0, 0);
    CP_COMMIT();
    load_stage(1, 64);
    CP_COMMIT();

    int st = 0;
    for (int c = 0; c < NC; c++) {
        CP_WAIT1();
        __syncthreads();
        if (c + 2 < NC) {
            int st2 = st + 2; if (st2 >= 3) st2 -= 3;
            load_stage(st2, (c+2) << 6);
            CP_COMMIT();
        }

        uint32_t base = sb + st*GS_STAGE;
        int arow = wm*64 + (lane & 15);
        int apl  = ((lane >> 4) & 1) << 4;
        int brow = wn*32 + ((lane >> 4) & 1)*8 + (lane & 7);
        int bpl  = ((lane >> 3) & 1) << 4;
#pragma unroll
        for (int kk = 0; kk < 4; kk++) {
            uint32_t a[4][4], b[2][4];
#pragma unroll
            for (int i = 0; i < 4; i++) {
                uint32_t sw = SMEM_SWIZZLE_128B((uint32_t)((arow + i*16)*128 + kk*32 + apl));
                ldsm4(a[i], base + sw);
            }
#pragma unroll
            for (int jp = 0; jp < 2; jp++) {
                uint32_t sw = SMEM_SWIZZLE_128B((uint32_t)((brow + jp*16)*128 + kk*32 + bpl));
                ldsm4(b[jp], base + GS_B + sw);
            }
#pragma unroll
            for (int i = 0; i < 4; i++) {
                mma16816(acc[i][0], a[i], b[0]);
                mma16816(acc[i][1], a[i], b[0] + 2);
                mma16816(acc[i][2], a[i], b[1]);
                mma16816(acc[i][3], a[i], b[1] + 2);
            }
        }
        if (++st == 3) st = 0;
    }

    float* Cp = (mode == 3) ? (C + (size_t)ks*M*N) : C;
#pragma unroll
    for (int i = 0; i < 4; i++) {
        int m0 = bm + wm*64 + i*16 + (lane >> 2);
#pragma unroll
        for (int j = 0; j < 4; j++) {
            int n = bn + wn*32 + j*8 + (lane & 3)*2;
            float v00 = acc[i][j][0], v01 = acc[i][j][1];
            float v10 = acc[i][j][2], v11 = acc[i][j][3];
            if (mode != 3) {
                float b0 = bias[n], b1 = bias[n+1];
                v00 += b0; v01 += b1; v10 += b0; v11 += b1;
            }
            if (mode == 0 || mode == 3) {
                float* c0 = Cp + (size_t)m0*N + n;
                float* c1 = Cp + (size_t)(m0+8)*N + n;
                c0[0] = v00; c0[1] = v01; c1[0] = v10; c1[1] = v11;
            } else {  // mode 1
                if (bn < 3*HIDN) {
                    *(uint32_t*)(lin1h + (size_t)m0*(3*HIDN) + n)     = packh2(v00, v01);
                    *(uint32_t*)(lin1h + (size_t)(m0+8)*(3*HIDN) + n) = packh2(v10, v11);
                } else {
                    int nc = HIDN + (n - 3*HIDN);
                    *(uint32_t*)(cat + (size_t)m0*CATN + nc)     = packh2(gelu_f(v00), gelu_f(v01));
                    *(uint32_t*)(cat + (size_t)(m0+8)*CATN + nc) = packh2(gelu_f(v10), gelu_f(v11));
                }
            }
        }
    }
}

// ---------------- qkv split: rmsnorm q/k + rope -> fp16 (fp16 input) ----------------
__global__ void qkv_norm_rope_kernel(const __half* __restrict__ lin1h,
                                     const float* __restrict__ qn_w, const float* __restrict__ kn_w,
                                     const float* __restrict__ cosT, const float* __restrict__ sinT,
                                     __half* __restrict__ qo, __half* __restrict__ ko,
                                     __half* __restrict__ vo) {
    int t = blockIdx.x, h = blockIdx.y, d = threadIdx.x;
    const __half* base = lin1h + (size_t)t*(3*HIDN) + h*DH;
    float q = __half2float(base[d]);
    float k = __half2float(base[HIDN + d]);
    __half v = base[2*HIDN + d];
    float s1 = q*q, s2 = k*k;
#pragma unroll
    for (int o = 16; o > 0; o >>= 1) {
        s1 += __shfl_down_sync(0xffffffffu, s1, o);
        s2 += __shfl_down_sync(0xffffffffu, s2, o);
    }
    __shared__ float red[8];
    int wid = d >> 5, lid = d & 31;
    if (lid == 0) { red[wid] = s1; red[4+wid] = s2; }
    __syncthreads();
    float qs = rsqrtf((red[0]+red[1]+red[2]+red[3]) * (1.f/DH) + 1e-6f);
    float ks = rsqrtf((red[4]+red[5]+red[6]+red[7]) * (1.f/DH) + 1e-6f);
    q = q * qs * qn_w[d];
    k = k * ks * kn_w[d];
    __shared__ float sq[DH], sk[DH];
    sq[d] = q; sk[d] = k;
    __syncthreads();
    if (t < IMGN) {
        int i = d >> 1;
        float c = cosT[t*(DH/2) + i], s = sinT[t*(DH/2) + i];
        float x1 = sq[2*i], x2 = sq[2*i+1];
        q = (d & 1) ? (x1*s + x2*c) : (x1*c - x2*s);
        x1 = sk[2*i]; x2 = sk[2*i+1];
        k = (d & 1) ? (x1*s + x2*c) : (x1*c - x2*s);
    }
    size_t o = ((size_t)t*NH + h)*DH + d;
    qo[o] = __float2half_rn(q);
    ko[o] = __float2half_rn(k);
    vo[o] = v;
}

__global__ void ref_norm_rope_kernel(const float* __restrict__ rk, const float* __restrict__ w,
                                     const float* __restrict__ cosT, const float* __restrict__ sinT,
                                     __half* __restrict__ out) {
    int t = blockIdx.x, h = blockIdx.y, d = threadIdx.x;
    const float* base = rk + (size_t)t*HIDN + h*DH;
    float kv = base[d];
    float s = kv*kv;
#pragma unroll
    for (int o = 16; o > 0; o >>= 1) s += __shfl_down_sync(0xffffffffu, s, o);
    __shared__ float red[4];
    int wid = d >> 5, lid = d & 31;
    if (lid == 0) red[wid] = s;
    __syncthreads();
    float kn = kv * rsqrtf((red[0]+red[1]+red[2]+red[3]) * (1.f/DH) + 1e-6f) * w[d];
    __shared__ float sk[DH];
    sk[d] = kn;
    __syncthreads();
    int i = d >> 1;
    float c = cosT[t*(DH/2) + i], sn = sinT[t*(DH/2) + i];
    float x1 = sk[2*i], x2 = sk[2*i+1];
    float r = (d & 1) ? (x1*sn + x2*c) : (x1*c - x2*sn);
    out[(size_t)t*HIDN + h*DH + d] = __float2half_rn(r);
}

// ---------------- fused dual flash attention (self + IP, fp16 cat output) ----------------
#define FAH_Q 0
#define FAH_K 32768
#define FAH_V 65536
#define FAH_SMEM 98304

__global__ void __launch_bounds__(256, 1) fa_dual_kernel(
    const __half* __restrict__ Q,
    const __half* __restrict__ K1, const __half* __restrict__ V1,
    const __half* __restrict__ K2, const __half* __restrict__ V2,
    __half* __restrict__ cat, int Lk1, int Lk2)
{
    extern __shared__ char smem[];
    uint32_t sb = smem_u32(smem);
    int tid = threadIdx.x, lane = tid & 31, wid = tid >> 5;
    int h = blockIdx.y;
    int q0 = blockIdx.x * 128;
    const float scale = 0.08838834764831845f;

#pragma unroll
    for (int qi = 0; qi < 8; qi++) {
        int idx = qi*256 + tid;
        int r = idx >> 4, ch = idx & 15;
        uint32_t ad = sb + FAH_Q + (ch>>3)*16384 + SMEM_SWIZZLE_128B((uint32_t)(r*128 + (ch&7)*16));
        cp16(ad, Q + (size_t)(q0+r)*HD + h*DH + ch*8);
    }
    CP_COMMIT();

    auto load_kv = [&](const __half* Kp, const __half* Vp, int s, int k0) {
        uint32_t kbs = sb + FAH_K + s*16384;
        uint32_t vbs = sb + FAH_V + s*16384;
#pragma unroll
        for (int qi = 0; qi < 4; qi++) {
            int idx = qi*256 + tid;
            int r = idx >> 4, ch = idx & 15;
            uint32_t off = (ch>>3)*8192 + SMEM_SWIZZLE_128B((uint32_t)(r*128 + (ch&7)*16));
            cp16(kbs + off, Kp + (size_t)(k0+r)*HD + h*DH + ch*8);
            cp16(vbs + off, Vp + (size_t)(k0+r)*HD + h*DH + ch*8);
        }
    };
    load_kv(K1, V1, 0, 0);
    CP_COMMIT();

    CP_WAIT1();
    __syncthreads();

    uint32_t qa[8][4];
    {
        int row = wid*16 + (lane & 7) + ((lane >> 3) & 1)*8;
#pragma unroll
        for (int kc = 0; kc < 8; kc++) {
            int d = kc*16 + ((lane >> 4) & 1)*8;
            uint32_t ad = sb + FAH_Q + (d>>6)*16384 + SMEM_SWIZZLE_128B((uint32_t)(row*128 + (d&63)*2));
            ldsm4(qa[kc], ad);
        }
    }

    float o[16][4];
    float m0, m1, l0, l1;
    uint32_t o1p[16][2];

    for (int phase = 0; phase < 2; phase++) {
        const __half* Kp = phase ? K2 : K1;
        const __half* Vp = phase ? V2 : V1;
        int Lk = phase ? Lk2 : Lk1;
#pragma unroll
        for (int i = 0; i < 16; i++)
#pragma unroll
            for (int j = 0; j < 4; j++) o[i][j] = 0.f;
        m0 = -1e30f; m1 = -1e30f; l0 = 0.f; l1 = 0.f;

        if (phase == 1) { load_kv(Kp, Vp, 0, 0); CP_COMMIT(); }

        int T = Lk >> 6;
        for (int t = 0; t < T; t++) {
            if (t + 1 < T) { load_kv(Kp, Vp, (t+1) & 1, (t+1) << 6); CP_COMMIT(); CP_WAIT1(); }
            else           { CP_WAIT0(); }
            __syncthreads();
            uint32_t kst = sb + FAH_K + (t & 1)*16384;
            uint32_t vst = sb + FAH_V + (t & 1)*16384;

            float c[8][4];
#pragma unroll
            for (int i = 0; i < 8; i++)
#pragma unroll
                for (int j = 0; j < 4; j++) c[i][j] = 0.f;

            int krow = (lane & 7) + ((lane >> 4) & 1)*8;
            int kpl  = ((lane >> 3) & 1)*8;
#pragma unroll
            for (int nb2 = 0; nb2 < 4; nb2++) {
                int row = nb2*16 + krow;
#pragma unroll
                for (int kc = 0; kc < 8; kc++) {
                    uint32_t bf[4];
                    int d = kc*16 + kpl;
                    uint32_t ad = kst + (d>>6)*8192 + SMEM_SWIZZLE_128B((uint32_t)(row*128 + (d&63)*2));
                    ldsm4(bf, ad);
                    mma16816(c[nb2*2],   qa[kc], bf);
                    mma16816(c[nb2*2+1], qa[kc], bf + 2);
                }
            }

            float mn0 = m0, mn1 = m1;
#pragma unroll
            for (int nb = 0; nb < 8; nb++) {
                c[nb][0] *= scale; c[nb][1] *= scale; c[nb][2] *= scale; c[nb][3] *= scale;
                mn0 = fmaxf(mn0, fmaxf(c[nb][0], c[nb][1]));
                mn1 = fmaxf(mn1, fmaxf(c[nb][2], c[nb][3]));
            }
            mn0 = fmaxf(mn0, __shfl_xor_sync(0xffffffffu, mn0, 1));
            mn0 = fmaxf(mn0, __shfl_xor_sync(0xffffffffu, mn0, 2));
            mn1 = fmaxf(mn1, __shfl_xor_sync(0xffffffffu, mn1, 1));
            mn1 = fmaxf(mn1, __shfl_xor_sync(0xffffffffu, mn1, 2));
            float a0 = __expf(m0 - mn0), a1 = __expf(m1 - mn1);
            m0 = mn0; m1 = mn1;
            float s0 = 0.f, s1 = 0.f;
#pragma unroll
            for (int nb = 0; nb < 8; nb++) {
                c[nb][0] = __expf(c[nb][0] - m0);
                c[nb][1] = __expf(c[nb][1] - m0);
                c[nb][2] = __expf(c[nb][2] - m1);
                c[nb][3] = __expf(c[nb][3] - m1);
                s0 += c[nb][0] + c[nb][1];
                s1 += c[nb][2] + c[nb][3];
            }
            s0 += __shfl_xor_sync(0xffffffffu, s0, 1);
            s0 += __shfl_xor_sync(0xffffffffu, s0, 2);
            s1 += __shfl_xor_sync(0xffffffffu, s1, 1);
            s1 += __shfl_xor_sync(0xffffffffu, s1, 2);
            l0 = l0*a0 + s0;
            l1 = l1*a1 + s1;

#pragma unroll
            for (int nb = 0; nb < 16; nb++) {
                o[nb][0] *= a0; o[nb][1] *= a0; o[nb][2] *= a1; o[nb][3] *= a1;
            }

            uint32_t pa[4][4];
#pragma unroll
            for (int kc2 = 0; kc2 < 4; kc2++) {
                pa[kc2][0] = packh2(c[2*kc2][0],   c[2*kc2][1]);
                pa[kc2][1] = packh2(c[2*kc2][2],   c[2*kc2][3]);
                pa[kc2][2] = packh2(c[2*kc2+1][0], c[2*kc2+1][1]);
                pa[kc2][3] = packh2(c[2*kc2+1][2], c[2*kc2+1][3]);
            }

            int vrow = (lane & 7) + ((lane >> 3) & 1)*8;
            int npl  = ((lane >> 4) & 1)*8;
#pragma unroll
            for (int kc2 = 0; kc2 < 4; kc2++) {
                int row = kc2*16 + vrow;
#pragma unroll
                for (int nbp = 0; nbp < 8; nbp++) {
                    uint32_t bf[4];
                    int n = nbp*16 + npl;
                    uint32_t ad = vst + (n>>6)*8192 + SMEM_SWIZZLE_128B((uint32_t)(row*128 + (n&63)*2));
                    ldsm4t(bf, ad);
                    mma16816(o[nbp*2],   pa[kc2], bf);
                    mma16816(o[nbp*2+1], pa[kc2], bf + 2);
                }
            }
            __syncthreads();
        }

        if (phase == 0) {
            float inv0 = 1.f / l0, inv1 = 1.f / l1;
#pragma unroll
            for (int nb = 0; nb < 16; nb++) {
                o1p[nb][0] = packh2(o[nb][0]*inv0, o[nb][1]*inv0);
                o1p[nb][1] = packh2(o[nb][2]*inv1, o[nb][3]*inv1);
            }
        }
    }

    float inv0 = 1.f / l0, inv1 = 1.f / l1;
    int r0 = q0 + wid*16 + (lane >> 2);
#pragma unroll
    for (int nb = 0; nb < 16; nb++) {
        int n = h*DH + nb*8 + (lane & 3)*2;
        float2 f0 = __half22float2(*(__half2*)&o1p[nb][0]);
        float2 f1 = __half22float2(*(__half2*)&o1p[nb][1]);
        uint32_t r0v = packh2(f0.x + o[nb][0]*inv0, f0.y + o[nb][1]*inv0);
        uint32_t r1v = packh2(f1.x + o[nb][2]*inv1, f1.y + o[nb][3]*inv1);
        *(uint32_t*)(cat + (size_t)r0*CATN + n)     = r0v;
        *(uint32_t*)(cat + (size_t)(r0+8)*CATN + n) = r1v;
    }
}

// ---------------- launcher ----------------
extern "C" void kernel_launch(void* const* d_in, const int* in_sizes, int n_in,
                              void* d_out, int out_size) {
    const float* x          = (const float*)d_in[0];
    const float* vec        = (const float*)d_in[1];
    const float* cosT       = (const float*)d_in[2];
    const float* sinT       = (const float*)d_in[3];
    const float* ref_latent = (const float*)d_in[4];
    const float* ref_cos    = (const float*)d_in[5];
    const float* ref_sin    = (const float*)d_in[6];
    const float* w_mod      = (const float*)d_in[7];
    const float* b_mod      = (const float*)d_in[8];
    const float* w1         = (const float*)d_in[9];
    const float* b1         = (const float*)d_in[10];
    const float* w2         = (const float*)d_in[11];
    const float* b2         = (const float*)d_in[12];
    const float* qn_w       = (const float*)d_in[13];
    const float* kn_w       = (const float*)d_in[14];
    const float* wk_ip      = (const float*)d_in[15];
    const float* bk_ip      = (const float*)d_in[16];
    const float* wv_ip      = (const float*)d_in[17];
    const float* bv_ip      = (const float*)d_in[18];
    const float* ref_kn_w   = (const float*)d_in[19];
    float* out = (float*)d_out;

    float *sv, *modb, *part, *refk, *refv;
    __half *xb, *lin1h, *cat, *rlb, *qb, *kb, *vb, *refkb, *refvb;
    __half *w1b, *w2b, *wkb, *wvb;
    cudaGetSymbolAddress((void**)&sv,     g_sv);
    cudaGetSymbolAddress((void**)&modb,   g_mod);
    cudaGetSymbolAddress((void**)&xb,     g_xb);
    cudaGetSymbolAddress((void**)&lin1h,  g_lin1h);
    cudaGetSymbolAddress((void**)&qb,     g_qb);
    cudaGetSymbolAddress((void**)&kb,     g_kb);
    cudaGetSymbolAddress((void**)&vb,     g_vb);
    cudaGetSymbolAddress((void**)&cat,    g_cat);
    cudaGetSymbolAddress((void**)&part,   g_part);
    cudaGetSymbolAddress((void**)&refk,   g_refk);
    cudaGetSymbolAddress((void**)&refv,   g_refv);
    cudaGetSymbolAddress((void**)&refkb,  g_refkb);
    cudaGetSymbolAddress((void**)&refvb,  g_refvb);
    cudaGetSymbolAddress((void**)&rlb,    g_rlb);
    cudaGetSymbolAddress((void**)&w1b,    g_w1b);
    cudaGetSymbolAddress((void**)&w2b,    g_w2b);
    cudaGetSymbolAddress((void**)&wkb,    g_wkb);
    cudaGetSymbolAddress((void**)&wvb,    g_wvb);

    cudaFuncSetAttribute(tc_gemm_kernel,
                         cudaFuncAttributeMaxDynamicSharedMemorySize, GK_SMEM_TOTAL);
    cudaFuncSetAttribute(fa_dual_kernel,
                         cudaFuncAttributeMaxDynamicSharedMemorySize, FAH_SMEM);

    static cudaStream_t s1 = nullptr, s2 = nullptr;
    static cudaEvent_t evRoot = nullptr, evW1 = nullptr, evRef = nullptr, evW2 = nullptr;
    if (!s1) {
        cudaStreamCreateWithFlags(&s1, cudaStreamNonBlocking);
        cudaStreamCreateWithFlags(&s2, cudaStreamNonBlocking);
        cudaEventCreateWithFlags(&evRoot, cudaEventDisableTiming);
        cudaEventCreateWithFlags(&evW1,   cudaEventDisableTiming);
        cudaEventCreateWithFlags(&evRef,  cudaEventDisableTiming);
        cudaEventCreateWithFlags(&evW2,   cudaEventDisableTiming);
    }

    dim3 tb(32, 8);

    // fork
    cudaEventRecord(evRoot, 0);
    cudaStreamWaitEvent(s1, evRoot, 0);
    cudaStreamWaitEvent(s2, evRoot, 0);

    // s1: w1 convert (feeds lin1 GEMM)
    wcvtT_kernel<<<dim3(L1N/32, HIDN/64), tb, 0, s1>>>(w1, w1b, HIDN, L1N);
    cudaEventRecord(evW1, s1);

    // s2: ref chain + w2 convert
    wcvtT_kernel<<<dim3(HIDN/32, HIDN/64), tb, 0, s2>>>(wk_ip, wkb, HIDN, HIDN);
    wcvtT_kernel<<<dim3(HIDN/32, HIDN/64), tb, 0, s2>>>(wv_ip, wvb, HIDN, HIDN);
    cvt_h_kernel<<<(REFN*HIDN + 255)/256, 256, 0, s2>>>(ref_latent, rlb, (size_t)REFN*HIDN);
    tc_gemm_kernel<<<(REFN/128)*(HIDN/128), 256, GK_SMEM_TOTAL, s2>>>(
        rlb, wkb, bk_ip, refk, nullptr, nullptr, REFN, HIDN, HIDN, HIDN, REFN/128, 0);
    tc_gemm_kernel<<<(REFN/128)*(HIDN/128), 256, GK_SMEM_TOTAL, s2>>>(
        rlb, wvb, bv_ip, refv, nullptr, nullptr, REFN, HIDN, HIDN, HIDN, REFN/128, 0);
    ref_norm_rope_kernel<<<dim3(REFN, NH), 128, 0, s2>>>(refk, ref_kn_w, ref_cos, ref_sin, refkb);
    cvt_h_kernel<<<(REFN*HIDN + 255)/256, 256, 0, s2>>>(refv, refvb, (size_t)REFN*HIDN);
    cudaEventRecord(evRef, s2);
    wcvtT_kernel<<<dim3(HIDN/32, CATN/64), tb, 0, s2>>>(w2, w2b, CATN, HIDN);
    cudaEventRecord(evW2, s2);

    // main stream: mod chain
    silu_kernel<<<12, 256>>>(vec, sv);
    modproj_kernel<<<(3*HIDN)/32, 256>>>(sv, w_mod, b_mod, modb);
    ln_mod_kernel<<<LTOT, 256>>>(x, modb, xb);

    // lin1 GEMM (qkv fp16 + gelu-cat fused)
    cudaStreamWaitEvent(0, evW1, 0);
    tc_gemm_kernel<<<(LTOT/128)*(L1N/128), 256, GK_SMEM_TOTAL>>>(
        xb, w1b, b1, nullptr, lin1h, cat, LTOT, L1N, HIDN, HIDN, LTOT/128, 1);

    // qkv norm/rope
    qkv_norm_rope_kernel<<<dim3(LTOT, NH), 128>>>(lin1h, qn_w, kn_w, cosT, sinT, qb, kb, vb);

    // fused dual attention (self + IP) -> fp16 cat
    cudaStreamWaitEvent(0, evRef, 0);
    fa_dual_kernel<<<dim3(LTOT/128, NH), 256, FAH_SMEM>>>(
        qb, kb, vb, refkb, refvb, cat, LTOT, REFN);

    // out GEMM: split-K=2 partials, then fused residual add
    cudaStreamWaitEvent(0, evW2, 0);
    tc_gemm_kernel<<<2*(LTOT/128)*(HIDN/128), 256, GK_SMEM_TOTAL>>>(
        cat, w2b, b2, part, nullptr, nullptr, LTOT, HIDN, CATN/2, CATN, LTOT/128, 3);
    final_add_kernel<<<(LTOT*HIDN)/(4*256), 256>>>(x, part, b2, modb + 2*HIDN, out);
}